// round 6
// baseline (speedup 1.0000x reference)
#include <cuda_runtime.h>
#include <math.h>

#define Bn 16
#define C  128
#define P  4096      // 64*64
#define TD 256
#define CD 256
#define E  8
#define NK 2

// ---------------- scratch ---------------------------------------------------
__device__ float g_xproj[Bn*C*P];       // x_proj
__device__ float g_pooled[Bn*C];        // SUM over pixels (mean applied in router)
__device__ int   g_eidx[Bn*NK];
__device__ float g_ew[Bn*NK];

__device__ __forceinline__ float silu_f(float v) {
    return v / (1.f + __expf(-v));
}

__device__ __forceinline__ float tf32r(float x) {
    unsigned u;
    asm("cvt.rna.tf32.f32 %0, %1;" : "=r"(u) : "f"(x));
    return __uint_as_float(u);
}

__device__ __forceinline__ void mma_tf32(float* c,
                                         unsigned a0, unsigned a1, unsigned a2, unsigned a3,
                                         unsigned b0, unsigned b1) {
    asm volatile("mma.sync.aligned.m16n8k8.row.col.f32.tf32.tf32.f32 "
                 "{%0,%1,%2,%3}, {%4,%5,%6,%7}, {%8,%9}, {%0,%1,%2,%3};"
                 : "+f"(c[0]), "+f"(c[1]), "+f"(c[2]), "+f"(c[3])
                 : "r"(a0), "r"(a1), "r"(a2), "r"(a3), "r"(b0), "r"(b1));
}

__device__ __forceinline__ void cp_async16(unsigned dst, const void* src) {
    asm volatile("cp.async.cg.shared.global [%0], [%1], 16;" :: "r"(dst), "l"(src));
}
__device__ __forceinline__ void cp_commit() {
    asm volatile("cp.async.commit_group;" ::: "memory");
}
__device__ __forceinline__ void cp_wait0() {
    asm volatile("cp.async.wait_group 0;" ::: "memory");
}

// stage layout: [16 ch][3 rows][68 floats] (row pad 64->68; 16B-aligned rows)
#define ST_ROW 68
#define ST_CH  (3 * ST_ROW)
// kick cp.async fill of stage for channels [c0, c0+16), rows y-1..y+1 (clamped)
__device__ __forceinline__ void kick_stage(unsigned stage_u32, const float* plane_base,
                                           int c0, int y, int tx) {
    #pragma unroll
    for (int s = 0; s < 3; s++) {
        int lin = s * 256 + tx;          // 0..767 = 16ch * 3rows * 16 f4
        int f4  = lin & 15;
        int kr  = lin >> 4;              // 0..47
        int r = kr % 3, k = kr / 3;
        int yy = y - 1 + r;
        yy = yy < 0 ? 0 : (yy > 63 ? 63 : yy);
        const float* src = plane_base + ((size_t)(c0 + k) << 12) + (yy << 6) + f4 * 4;
        unsigned dst = stage_u32 + ((unsigned)(k * ST_CH + r * ST_ROW + f4 * 4) << 2);
        cp_async16(dst, src);
    }
    cp_commit();
}

// dw 3x3 on one quad from staged rows (row r valid iff y-1+r in [0,64))
__device__ __forceinline__ void dw_quad_st(const float* st_ch, int y, int px0,
                                           const float* wc, float bb,
                                           float& a0, float& a1, float& a2, float& a3) {
    a0 = bb; a1 = bb; a2 = bb; a3 = bb;
    #pragma unroll
    for (int r = 0; r < 3; r++) {
        if (r == 0 && y == 0)  continue;
        if (r == 2 && y == 63) continue;
        const float* row = st_ch + r * ST_ROW;
        float4 m = *(const float4*)&row[px0];
        float rl = (px0 == 0)  ? 0.f : row[px0 - 1];
        float rr = (px0 == 60) ? 0.f : row[px0 + 4];
        float w0 = wc[r*3], w1 = wc[r*3+1], w2 = wc[r*3+2];
        a0 += w0*rl  + w1*m.x + w2*m.y;
        a1 += w0*m.x + w1*m.y + w2*m.z;
        a2 += w0*m.y + w1*m.z + w2*m.w;
        a3 += w0*m.z + w1*m.w + w2*rr;
    }
}

// ---------------- 0) zero pooled accumulator --------------------------------
__global__ void zero_pooled_kernel() {
    int t = blockIdx.x * blockDim.x + threadIdx.x;
    if (t < Bn * C) g_pooled[t] = 0.f;
}

// ---------------- 1) fused proj: dw3x3 -> pw GEMM (tf32) -> pool ------------
// grid (64 rows, 16 b), 256 thr, KC=16. smem ~27.9KB.
#define WS 20       // Wsm row stride KC=16 (conflict-free A-frag: bank=(20g+t4)%32)
#define BS 72       // Bsm row stride (conflict-free B-frag: bank=8*t4+g)
__global__ __launch_bounds__(256)
void fused_proj_kernel(const float* __restrict__ x,
                       const float* __restrict__ dw_w, const float* __restrict__ dw_b,
                       const float* __restrict__ Wm,   const float* __restrict__ bias) {
    int y  = blockIdx.x;
    int b  = blockIdx.y;
    int tx = threadIdx.x;
    int wid = tx >> 5, lane = tx & 31;
    int wm = wid >> 1, wn = wid & 1;
    int g = lane >> 2, t4 = lane & 3;
    __shared__ float Wsm[128 * WS];
    __shared__ float Bsm[16 * BS];
    __shared__ float stage[16 * ST_CH];
    unsigned stage_u32 = (unsigned)__cvta_generic_to_shared(stage);
    const float* plane_base = x + (((size_t)b * C) << 12);

    float acc[2][4][4];
    #pragma unroll
    for (int i = 0; i < 2; i++)
        #pragma unroll
        for (int j = 0; j < 4; j++)
            #pragma unroll
            for (int l = 0; l < 4; l++) acc[i][j][l] = 0.f;

    kick_stage(stage_u32, plane_base, 0, y, tx);

    int dwk = tx >> 4, dwpx = (tx & 15) << 2;
    for (int c0 = 0; c0 < C; c0 += 16) {
        cp_wait0();
        __syncthreads();                       // stage ready; prev MMA done
        // W raw loads first (L2 latency hidden behind dw compute)
        float4 wraw[2]; int wco[2], wk4[2];
        #pragma unroll
        for (int i = 0; i < 2; i++) {
            int slot = i * 256 + tx;
            wco[i] = slot >> 2; wk4[i] = slot & 3;
            wraw[i] = *(const float4*)&Wm[wco[i] * C + c0 + wk4[i] * 4];
        }
        // dw from staged smem
        {
            int c = c0 + dwk;
            float a0, a1, a2, a3;
            dw_quad_st(&stage[dwk * ST_CH], y, dwpx, dw_w + c * 9, dw_b[c], a0, a1, a2, a3);
            float* d = &Bsm[dwk * BS + dwpx];
            d[0] = tf32r(a0); d[1] = tf32r(a1); d[2] = tf32r(a2); d[3] = tf32r(a3);
        }
        // W cvt + store
        #pragma unroll
        for (int i = 0; i < 2; i++) {
            float* d = &Wsm[wco[i] * WS + wk4[i] * 4];
            d[0] = tf32r(wraw[i].x); d[1] = tf32r(wraw[i].y);
            d[2] = tf32r(wraw[i].z); d[3] = tf32r(wraw[i].w);
        }
        __syncthreads();                       // Bsm/Wsm ready; stage reads done
        if (c0 + 16 < C) kick_stage(stage_u32, plane_base, c0 + 16, y, tx);
        #pragma unroll
        for (int kk = 0; kk < 2; kk++) {
            int kb = kk * 8;
            unsigned af[2][4];
            #pragma unroll
            for (int mt = 0; mt < 2; mt++) {
                int r0 = wm * 32 + mt * 16 + g;
                af[mt][0] = __float_as_uint(Wsm[r0 * WS + kb + t4]);
                af[mt][1] = __float_as_uint(Wsm[(r0 + 8) * WS + kb + t4]);
                af[mt][2] = __float_as_uint(Wsm[r0 * WS + kb + t4 + 4]);
                af[mt][3] = __float_as_uint(Wsm[(r0 + 8) * WS + kb + t4 + 4]);
            }
            #pragma unroll
            for (int nt = 0; nt < 4; nt++) {
                int col = wn * 32 + nt * 8 + g;
                unsigned b0 = __float_as_uint(Bsm[(kb + t4) * BS + col]);
                unsigned b1 = __float_as_uint(Bsm[(kb + t4 + 4) * BS + col]);
                #pragma unroll
                for (int mt = 0; mt < 2; mt++)
                    mma_tf32(acc[mt][nt], af[mt][0], af[mt][1], af[mt][2], af[mt][3], b0, b1);
            }
        }
    }
    // epilogue: bias, store xproj row, pooled partials
    #pragma unroll
    for (int mt = 0; mt < 2; mt++) {
        int r0 = wm * 32 + mt * 16 + g;
        float bb0 = bias[r0], bb8 = bias[r0 + 8];
        float s0 = 0.f, s8 = 0.f;
        #pragma unroll
        for (int nt = 0; nt < 4; nt++) {
            int col = (y << 6) + wn * 32 + nt * 8 + 2 * t4;
            float* o0 = g_xproj + ((((size_t)b * C) + r0) << 12) + col;
            float* o8 = g_xproj + ((((size_t)b * C) + r0 + 8) << 12) + col;
            float v0 = acc[mt][nt][0] + bb0, v1 = acc[mt][nt][1] + bb0;
            float v2 = acc[mt][nt][2] + bb8, v3 = acc[mt][nt][3] + bb8;
            *(float2*)o0 = make_float2(v0, v1);
            *(float2*)o8 = make_float2(v2, v3);
            s0 += v0 + v1; s8 += v2 + v3;
        }
        s0 += __shfl_down_sync(0xffffffffu, s0, 2, 4);
        s0 += __shfl_down_sync(0xffffffffu, s0, 1, 4);
        s8 += __shfl_down_sync(0xffffffffu, s8, 2, 4);
        s8 += __shfl_down_sync(0xffffffffu, s8, 1, 4);
        if (t4 == 0) {
            atomicAdd(&g_pooled[b * C + r0], s0);
            atomicAdd(&g_pooled[b * C + r0 + 8], s8);
        }
    }
}

// ---------------- 2) router: per-b block, fused MLP+top2 -------------------
__global__ __launch_bounds__(1024)
void router_kernel(const float* __restrict__ t_emb,
                   const float* __restrict__ c_emb,
                   const float* __restrict__ W1, const float* __restrict__ b1,
                   const float* __restrict__ W2, const float* __restrict__ b2,
                   float* __restrict__ out_logits) {
    int b = blockIdx.x;
    __shared__ float feat[C + TD + CD];
    __shared__ float hpart[8][C];
    __shared__ float h[C];
    __shared__ float lgp[8][E];
    __shared__ float lg[E];
    int t = threadIdx.x;
    if (t < C + TD + CD) {
        float v;
        if (t < C)            v = g_pooled[b * C + t] * (1.f / 4096.f);
        else if (t < C + TD)  v = t_emb[b * TD + (t - C)];
        else                  v = c_emb[b * CD + (t - C - TD)];
        feat[t] = v;
    }
    __syncthreads();
    int co = t & 127, chunk = t >> 7;
    {
        float a0 = 0.f, a1 = 0.f, a2 = 0.f, a3 = 0.f;
        int f0 = chunk * 80;
        #pragma unroll
        for (int f = f0; f < f0 + 80; f += 4) {
            a0 += feat[f]     * W1[f * C + co];
            a1 += feat[f + 1] * W1[(f + 1) * C + co];
            a2 += feat[f + 2] * W1[(f + 2) * C + co];
            a3 += feat[f + 3] * W1[(f + 3) * C + co];
        }
        hpart[chunk][co] = (a0 + a1) + (a2 + a3);
    }
    __syncthreads();
    if (t < C) {
        float v = b1[t];
        #pragma unroll
        for (int i = 0; i < 8; i++) v += hpart[i][t];
        h[t] = silu_f(v);
    }
    __syncthreads();
    if (t < 64) {
        int e = t & 7, pp = t >> 3;
        float a = 0.f;
        int c0 = pp * 16;
        #pragma unroll
        for (int ci = c0; ci < c0 + 16; ci++) a += h[ci] * W2[ci * E + e];
        lgp[pp][e] = a;
    }
    __syncthreads();
    if (t < E) {
        float a = b2[t];
        #pragma unroll
        for (int i = 0; i < 8; i++) a += lgp[i][t];
        lg[t] = a;
        out_logits[b * E + t] = a;
    }
    __syncthreads();
    if (t == 0) {
        int i0 = 0; float v0 = lg[0];
        for (int e = 1; e < E; e++) if (lg[e] > v0) { v0 = lg[e]; i0 = e; }
        int i1 = -1; float v1 = -3.0e38f;
        for (int e = 0; e < E; e++) {
            if (e == i0) continue;
            if (lg[e] > v1) { v1 = lg[e]; i1 = e; }
        }
        float w0 = 1.f / (1.f + __expf(v1 - v0));
        g_eidx[b*2]   = i0;  g_eidx[b*2+1] = i1;
        g_ew[b*2]     = w0;  g_ew[b*2+1]   = 1.f - w0;
    }
}

// ---------------- 3) fused experts: dw3x3 x2 -> pw GEMM x2 -> silu+mix -----
// grid (64 rows, 16 b), 256 thr, KC=16. smem ~42.8KB.
__global__ __launch_bounds__(256)
void fused_exp_kernel(const float* __restrict__ dw_w, const float* __restrict__ dw_b,
                      const float* __restrict__ Wm,   const float* __restrict__ bias,
                      float* __restrict__ out) {
    int y  = blockIdx.x;
    int b  = blockIdx.y;
    int tx = threadIdx.x;
    int wid = tx >> 5, lane = tx & 31;
    int wm = wid >> 1, wn = wid & 1;
    int g = lane >> 2, t4 = lane & 3;
    int e0 = g_eidx[b*2], e1 = g_eidx[b*2+1];
    float rw0 = g_ew[b*2], rw1 = g_ew[b*2+1];
    __shared__ float Wsm0[128 * WS], Wsm1[128 * WS];
    __shared__ float Bsm0[16 * BS],  Bsm1[16 * BS];
    __shared__ float stage[16 * ST_CH];
    unsigned stage_u32 = (unsigned)__cvta_generic_to_shared(stage);
    const float* plane_base = g_xproj + (((size_t)b * C) << 12);
    const float* W0 = Wm + (size_t)e0 * C * C;
    const float* W1 = Wm + (size_t)e1 * C * C;

    float a0c[2][4][4], a1c[2][4][4];
    #pragma unroll
    for (int i = 0; i < 2; i++)
        #pragma unroll
        for (int j = 0; j < 4; j++)
            #pragma unroll
            for (int l = 0; l < 4; l++) { a0c[i][j][l] = 0.f; a1c[i][j][l] = 0.f; }

    kick_stage(stage_u32, plane_base, 0, y, tx);

    int dwk = tx >> 4, dwpx = (tx & 15) << 2;
    for (int c0 = 0; c0 < C; c0 += 16) {
        cp_wait0();
        __syncthreads();
        // W raw loads (both experts) first
        float4 wraw0[2], wraw1[2]; int wco[2], wk4[2];
        #pragma unroll
        for (int i = 0; i < 2; i++) {
            int slot = i * 256 + tx;
            wco[i] = slot >> 2; wk4[i] = slot & 3;
            wraw0[i] = *(const float4*)&W0[wco[i] * C + c0 + wk4[i] * 4];
            wraw1[i] = *(const float4*)&W1[wco[i] * C + c0 + wk4[i] * 4];
        }
        // dw both experts from staged smem
        {
            int c = c0 + dwk;
            const float* st_ch = &stage[dwk * ST_CH];
            const float* wcA = dw_w + ((size_t)e0 * C + c) * 9;
            const float* wcB = dw_w + ((size_t)e1 * C + c) * 9;
            float bA = dw_b[e0 * C + c], bB = dw_b[e1 * C + c];
            float A0 = bA, A1 = bA, A2 = bA, A3 = bA;
            float B0 = bB, B1 = bB, B2 = bB, B3 = bB;
            #pragma unroll
            for (int r = 0; r < 3; r++) {
                if (r == 0 && y == 0)  continue;
                if (r == 2 && y == 63) continue;
                const float* row = st_ch + r * ST_ROW;
                float4 m = *(const float4*)&row[dwpx];
                float rl = (dwpx == 0)  ? 0.f : row[dwpx - 1];
                float rr = (dwpx == 60) ? 0.f : row[dwpx + 4];
                float wa0 = wcA[r*3], wa1 = wcA[r*3+1], wa2 = wcA[r*3+2];
                float wb0 = wcB[r*3], wb1 = wcB[r*3+1], wb2 = wcB[r*3+2];
                A0 += wa0*rl  + wa1*m.x + wa2*m.y;
                A1 += wa0*m.x + wa1*m.y + wa2*m.z;
                A2 += wa0*m.y + wa1*m.z + wa2*m.w;
                A3 += wa0*m.z + wa1*m.w + wa2*rr;
                B0 += wb0*rl  + wb1*m.x + wb2*m.y;
                B1 += wb0*m.x + wb1*m.y + wb2*m.z;
                B2 += wb0*m.y + wb1*m.z + wb2*m.w;
                B3 += wb0*m.z + wb1*m.w + wb2*rr;
            }
            float* d0 = &Bsm0[dwk * BS + dwpx];
            float* d1 = &Bsm1[dwk * BS + dwpx];
            d0[0]=tf32r(A0); d0[1]=tf32r(A1); d0[2]=tf32r(A2); d0[3]=tf32r(A3);
            d1[0]=tf32r(B0); d1[1]=tf32r(B1); d1[2]=tf32r(B2); d1[3]=tf32r(B3);
        }
        // W cvt + store
        #pragma unroll
        for (int i = 0; i < 2; i++) {
            float* d0 = &Wsm0[wco[i] * WS + wk4[i] * 4];
            float* d1 = &Wsm1[wco[i] * WS + wk4[i] * 4];
            d0[0]=tf32r(wraw0[i].x); d0[1]=tf32r(wraw0[i].y);
            d0[2]=tf32r(wraw0[i].z); d0[3]=tf32r(wraw0[i].w);
            d1[0]=tf32r(wraw1[i].x); d1[1]=tf32r(wraw1[i].y);
            d1[2]=tf32r(wraw1[i].z); d1[3]=tf32r(wraw1[i].w);
        }
        __syncthreads();
        if (c0 + 16 < C) kick_stage(stage_u32, plane_base, c0 + 16, y, tx);
        #pragma unroll
        for (int kk = 0; kk < 2; kk++) {
            int kb = kk * 8;
            unsigned af0[2][4], af1[2][4];
            #pragma unroll
            for (int mt = 0; mt < 2; mt++) {
                int r0 = wm * 32 + mt * 16 + g;
                af0[mt][0] = __float_as_uint(Wsm0[r0 * WS + kb + t4]);
                af0[mt][1] = __float_as_uint(Wsm0[(r0 + 8) * WS + kb + t4]);
                af0[mt][2] = __float_as_uint(Wsm0[r0 * WS + kb + t4 + 4]);
                af0[mt][3] = __float_as_uint(Wsm0[(r0 + 8) * WS + kb + t4 + 4]);
                af1[mt][0] = __float_as_uint(Wsm1[r0 * WS + kb + t4]);
                af1[mt][1] = __float_as_uint(Wsm1[(r0 + 8) * WS + kb + t4]);
                af1[mt][2] = __float_as_uint(Wsm1[r0 * WS + kb + t4 + 4]);
                af1[mt][3] = __float_as_uint(Wsm1[(r0 + 8) * WS + kb + t4 + 4]);
            }
            #pragma unroll
            for (int nt = 0; nt < 4; nt++) {
                int col = wn * 32 + nt * 8 + g;
                unsigned b00 = __float_as_uint(Bsm0[(kb + t4) * BS + col]);
                unsigned b01 = __float_as_uint(Bsm0[(kb + t4 + 4) * BS + col]);
                unsigned b10 = __float_as_uint(Bsm1[(kb + t4) * BS + col]);
                unsigned b11 = __float_as_uint(Bsm1[(kb + t4 + 4) * BS + col]);
                #pragma unroll
                for (int mt = 0; mt < 2; mt++) {
                    mma_tf32(a0c[mt][nt], af0[mt][0], af0[mt][1], af0[mt][2], af0[mt][3], b00, b01);
                    mma_tf32(a1c[mt][nt], af1[mt][0], af1[mt][1], af1[mt][2], af1[mt][3], b10, b11);
                }
            }
        }
    }
    #pragma unroll
    for (int mt = 0; mt < 2; mt++) {
        int r0 = wm * 32 + mt * 16 + g;
        float b00 = bias[e0 * C + r0], b08 = bias[e0 * C + r0 + 8];
        float b10 = bias[e1 * C + r0], b18 = bias[e1 * C + r0 + 8];
        #pragma unroll
        for (int nt = 0; nt < 4; nt++) {
            int col = (y << 6) + wn * 32 + nt * 8 + 2 * t4;
            float* o0 = out + ((((size_t)b * C) + r0) << 12) + col;
            float* o8 = out + ((((size_t)b * C) + r0 + 8) << 12) + col;
            float v0 = rw0 * silu_f(a0c[mt][nt][0] + b00) + rw1 * silu_f(a1c[mt][nt][0] + b10);
            float v1 = rw0 * silu_f(a0c[mt][nt][1] + b00) + rw1 * silu_f(a1c[mt][nt][1] + b10);
            float v2 = rw0 * silu_f(a0c[mt][nt][2] + b08) + rw1 * silu_f(a1c[mt][nt][2] + b18);
            float v3 = rw0 * silu_f(a0c[mt][nt][3] + b08) + rw1 * silu_f(a1c[mt][nt][3] + b18);
            *(float2*)o0 = make_float2(v0, v1);
            *(float2*)o8 = make_float2(v2, v3);
        }
    }
}

// ---------------- launch ----------------------------------------------------
extern "C" void kernel_launch(void* const* d_in, const int* in_sizes, int n_in,
                              void* d_out, int out_size) {
    const float* x         = (const float*)d_in[0];
    const float* t_emb     = (const float*)d_in[1];
    const float* c_emb     = (const float*)d_in[2];
    const float* proj_dw   = (const float*)d_in[3];
    const float* proj_dw_b = (const float*)d_in[4];
    const float* proj_pw   = (const float*)d_in[5];
    const float* proj_pw_b = (const float*)d_in[6];
    const float* r_w1      = (const float*)d_in[7];
    const float* r_b1      = (const float*)d_in[8];
    const float* r_w2      = (const float*)d_in[9];
    const float* r_b2      = (const float*)d_in[10];
    const float* exp_dw    = (const float*)d_in[11];
    const float* exp_dw_b  = (const float*)d_in[12];
    const float* exp_pw    = (const float*)d_in[13];
    const float* exp_pw_b  = (const float*)d_in[14];

    float* out        = (float*)d_out;
    float* out_logits = out + (size_t)Bn * C * P;

    zero_pooled_kernel<<<(Bn*C + 255) / 256, 256>>>();
    fused_proj_kernel<<<dim3(64, Bn), 256>>>(x, proj_dw, proj_dw_b, proj_pw, proj_pw_b);
    router_kernel<<<Bn, 1024>>>(t_emb, c_emb, r_w1, r_b1, r_w2, r_b2, out_logits);
    fused_exp_kernel<<<dim3(64, Bn), 256>>>(exp_dw, exp_dw_b, exp_pw, exp_pw_b, out);
}

// round 7
// speedup vs baseline: 1.2688x; 1.2688x over previous
#include <cuda_runtime.h>
#include <math.h>

#define Bn 16
#define C  128
#define P  4096      // 64*64
#define TD 256
#define CD 256
#define E  8
#define NK 2

// ---------------- scratch (static device arrays) ---------------------------
__device__ float g_t1[Bn*C*P];          // dwconv(proj) output
__device__ float g_xproj[Bn*C*P];       // x_proj
__device__ float g_t2[Bn*NK*C*P];       // expert dwconv outputs (routed)
__device__ float g_pooled[Bn*C];        // SUM over pixels (mean in router)
__device__ int   g_eidx[Bn*NK];
__device__ float g_ew[Bn*NK];

__device__ __forceinline__ float silu_f(float v) {
    return v / (1.f + __expf(-v));
}

__device__ __forceinline__ float tf32r(float x) {
    unsigned u;
    asm("cvt.rna.tf32.f32 %0, %1;" : "=r"(u) : "f"(x));
    return __uint_as_float(u);
}

__device__ __forceinline__ void mma_tf32(float* c,
                                         unsigned a0, unsigned a1, unsigned a2, unsigned a3,
                                         unsigned b0, unsigned b1) {
    asm volatile("mma.sync.aligned.m16n8k8.row.col.f32.tf32.tf32.f32 "
                 "{%0,%1,%2,%3}, {%4,%5,%6,%7}, {%8,%9}, {%0,%1,%2,%3};"
                 : "+f"(c[0]), "+f"(c[1]), "+f"(c[2]), "+f"(c[3])
                 : "r"(a0), "r"(a1), "r"(a2), "r"(a3), "r"(b0), "r"(b1));
}

// ---------------- 0) zero pooled accumulator --------------------------------
__global__ void zero_pooled_kernel() {
    int t = blockIdx.x * blockDim.x + threadIdx.x;
    if (t < Bn * C) g_pooled[t] = 0.f;
}

// ---------------- 1) proj depthwise 3x3 (4 px / thread) --------------------
__global__ void dw_proj_kernel(const float* __restrict__ x,
                               const float* __restrict__ w,
                               const float* __restrict__ bias) {
    int idx = blockIdx.x * blockDim.x + threadIdx.x;   // over Bn*C*1024
    if (idx >= Bn*C*1024) return;
    int q = idx & 1023;
    int px0 = (q & 15) << 2;
    int py  = q >> 4;
    int plane = idx >> 10;            // b*C + c
    int c = plane & 127;
    const float* xp = x + ((size_t)plane << 12);
    const float* wc = w + c * 9;
    float bb = bias[c];
    float acc0 = bb, acc1 = bb, acc2 = bb, acc3 = bb;
    #pragma unroll
    for (int dy = -1; dy <= 1; dy++) {
        int yy = py + dy;
        if ((unsigned)yy >= 64u) continue;
        const float* row = xp + (yy << 6);
        float4 m = *(const float4*)&row[px0];
        float rl = (px0 == 0)  ? 0.f : row[px0 - 1];
        float rr = (px0 == 60) ? 0.f : row[px0 + 4];
        float w0 = wc[(dy+1)*3], w1 = wc[(dy+1)*3+1], w2 = wc[(dy+1)*3+2];
        acc0 += w0*rl  + w1*m.x + w2*m.y;
        acc1 += w0*m.x + w1*m.y + w2*m.z;
        acc2 += w0*m.y + w1*m.z + w2*m.w;
        acc3 += w0*m.z + w1*m.w + w2*rr;
    }
    *(float4*)&g_t1[((size_t)plane << 12) + (py << 6) + px0] =
        make_float4(acc0, acc1, acc2, acc3);
}

// ---------------- 2) proj pw GEMM (tf32, pipelined) + fused pool -----------
// 256 thr, block tile 128co x 64px, KC=32, reg-prefetch pipeline.
#define WS_P 36     // Wsm stride KC=32: A-frag bank=(4g+t4) conflict-free
#define BS_S 72     // Bsm stride: B-frag bank=(8t4+g) conflict-free
__global__ __launch_bounds__(256)
void pw_proj_kernel(const float* __restrict__ Wm, const float* __restrict__ bias) {
    int b  = blockIdx.y;
    int p0 = blockIdx.x * 64;
    int tx = threadIdx.x;
    int wid = tx >> 5, lane = tx & 31;
    int wm = wid >> 1, wn = wid & 1;
    int g = lane >> 2, t4 = lane & 3;
    __shared__ float Wsm[128 * WS_P];
    __shared__ float Bsm[32 * BS_S];
    float acc[2][4][4];
    #pragma unroll
    for (int i = 0; i < 2; i++)
        #pragma unroll
        for (int j = 0; j < 4; j++)
            #pragma unroll
            for (int l = 0; l < 4; l++) acc[i][j][l] = 0.f;

    const float* tin = g_t1 + (((size_t)b * C) << 12) + p0;
    // fixed slot mapping
    int wco[4], wk4[4], bk[2], bpx[2];
    #pragma unroll
    for (int i = 0; i < 4; i++) { int s = i * 256 + tx; wco[i] = s >> 3; wk4[i] = s & 7; }
    #pragma unroll
    for (int i = 0; i < 2; i++) { int s = i * 256 + tx; bk[i] = s >> 4; bpx[i] = s & 15; }

    float4 wraw[4], braw[2];
    #pragma unroll
    for (int i = 0; i < 4; i++) wraw[i] = *(const float4*)&Wm[wco[i] * C + wk4[i] * 4];
    #pragma unroll
    for (int i = 0; i < 2; i++) braw[i] = *(const float4*)&tin[(size_t)bk[i] * P + bpx[i] * 4];

    for (int ci = 0; ci < 4; ci++) {
        #pragma unroll
        for (int i = 0; i < 4; i++) {
            float* d = &Wsm[wco[i] * WS_P + wk4[i] * 4];
            d[0] = tf32r(wraw[i].x); d[1] = tf32r(wraw[i].y);
            d[2] = tf32r(wraw[i].z); d[3] = tf32r(wraw[i].w);
        }
        #pragma unroll
        for (int i = 0; i < 2; i++) {
            float* d = &Bsm[bk[i] * BS_S + bpx[i] * 4];
            d[0] = tf32r(braw[i].x); d[1] = tf32r(braw[i].y);
            d[2] = tf32r(braw[i].z); d[3] = tf32r(braw[i].w);
        }
        __syncthreads();
        if (ci < 3) {                         // prefetch next chunk (hidden by MMA)
            int c0 = (ci + 1) * 32;
            #pragma unroll
            for (int i = 0; i < 4; i++)
                wraw[i] = *(const float4*)&Wm[wco[i] * C + c0 + wk4[i] * 4];
            #pragma unroll
            for (int i = 0; i < 2; i++)
                braw[i] = *(const float4*)&tin[(size_t)(c0 + bk[i]) * P + bpx[i] * 4];
        }
        #pragma unroll
        for (int kk = 0; kk < 4; kk++) {
            int kb = kk * 8;
            unsigned af[2][4];
            #pragma unroll
            for (int mt = 0; mt < 2; mt++) {
                int r0 = wm * 32 + mt * 16 + g;
                af[mt][0] = __float_as_uint(Wsm[r0 * WS_P + kb + t4]);
                af[mt][1] = __float_as_uint(Wsm[(r0 + 8) * WS_P + kb + t4]);
                af[mt][2] = __float_as_uint(Wsm[r0 * WS_P + kb + t4 + 4]);
                af[mt][3] = __float_as_uint(Wsm[(r0 + 8) * WS_P + kb + t4 + 4]);
            }
            #pragma unroll
            for (int nt = 0; nt < 4; nt++) {
                int col = wn * 32 + nt * 8 + g;
                unsigned b0 = __float_as_uint(Bsm[(kb + t4) * BS_S + col]);
                unsigned b1 = __float_as_uint(Bsm[(kb + t4 + 4) * BS_S + col]);
                #pragma unroll
                for (int mt = 0; mt < 2; mt++)
                    mma_tf32(acc[mt][nt], af[mt][0], af[mt][1], af[mt][2], af[mt][3], b0, b1);
            }
        }
        __syncthreads();
    }
    // epilogue: bias, store xproj, pooled partials
    #pragma unroll
    for (int mt = 0; mt < 2; mt++) {
        int r0 = wm * 32 + mt * 16 + g;
        float bb0 = bias[r0], bb8 = bias[r0 + 8];
        float s0 = 0.f, s8 = 0.f;
        #pragma unroll
        for (int nt = 0; nt < 4; nt++) {
            int col = p0 + wn * 32 + nt * 8 + 2 * t4;
            float* o0 = g_xproj + ((((size_t)b * C) + r0) << 12) + col;
            float* o8 = g_xproj + ((((size_t)b * C) + r0 + 8) << 12) + col;
            float v0 = acc[mt][nt][0] + bb0, v1 = acc[mt][nt][1] + bb0;
            float v2 = acc[mt][nt][2] + bb8, v3 = acc[mt][nt][3] + bb8;
            *(float2*)o0 = make_float2(v0, v1);
            *(float2*)o8 = make_float2(v2, v3);
            s0 += v0 + v1; s8 += v2 + v3;
        }
        s0 += __shfl_down_sync(0xffffffffu, s0, 2, 4);
        s0 += __shfl_down_sync(0xffffffffu, s0, 1, 4);
        s8 += __shfl_down_sync(0xffffffffu, s8, 2, 4);
        s8 += __shfl_down_sync(0xffffffffu, s8, 1, 4);
        if (t4 == 0) {
            atomicAdd(&g_pooled[b * C + r0], s0);
            atomicAdd(&g_pooled[b * C + r0 + 8], s8);
        }
    }
}

// ---------------- 3) router: per-b block, fused MLP+top2 -------------------
__global__ __launch_bounds__(1024)
void router_kernel(const float* __restrict__ t_emb,
                   const float* __restrict__ c_emb,
                   const float* __restrict__ W1, const float* __restrict__ b1,
                   const float* __restrict__ W2, const float* __restrict__ b2,
                   float* __restrict__ out_logits) {
    int b = blockIdx.x;
    __shared__ float feat[C + TD + CD];
    __shared__ float hpart[8][C];
    __shared__ float h[C];
    __shared__ float lgp[8][E];
    __shared__ float lg[E];
    int t = threadIdx.x;
    if (t < C + TD + CD) {
        float v;
        if (t < C)            v = g_pooled[b * C + t] * (1.f / 4096.f);
        else if (t < C + TD)  v = t_emb[b * TD + (t - C)];
        else                  v = c_emb[b * CD + (t - C - TD)];
        feat[t] = v;
    }
    __syncthreads();
    int co = t & 127, chunk = t >> 7;
    {
        float a0 = 0.f, a1 = 0.f, a2 = 0.f, a3 = 0.f;
        int f0 = chunk * 80;
        #pragma unroll
        for (int f = f0; f < f0 + 80; f += 4) {
            a0 += feat[f]     * W1[f * C + co];
            a1 += feat[f + 1] * W1[(f + 1) * C + co];
            a2 += feat[f + 2] * W1[(f + 2) * C + co];
            a3 += feat[f + 3] * W1[(f + 3) * C + co];
        }
        hpart[chunk][co] = (a0 + a1) + (a2 + a3);
    }
    __syncthreads();
    if (t < C) {
        float v = b1[t];
        #pragma unroll
        for (int i = 0; i < 8; i++) v += hpart[i][t];
        h[t] = silu_f(v);
    }
    __syncthreads();
    if (t < 64) {
        int e = t & 7, pp = t >> 3;
        float a = 0.f;
        int c0 = pp * 16;
        #pragma unroll
        for (int ci = c0; ci < c0 + 16; ci++) a += h[ci] * W2[ci * E + e];
        lgp[pp][e] = a;
    }
    __syncthreads();
    if (t < E) {
        float a = b2[t];
        #pragma unroll
        for (int i = 0; i < 8; i++) a += lgp[i][t];
        lg[t] = a;
        out_logits[b * E + t] = a;
    }
    __syncthreads();
    if (t == 0) {
        int i0 = 0; float v0 = lg[0];
        for (int e = 1; e < E; e++) if (lg[e] > v0) { v0 = lg[e]; i0 = e; }
        int i1 = -1; float v1 = -3.0e38f;
        for (int e = 0; e < E; e++) {
            if (e == i0) continue;
            if (lg[e] > v1) { v1 = lg[e]; i1 = e; }
        }
        float w0 = 1.f / (1.f + __expf(v1 - v0));
        g_eidx[b*2]   = i0;  g_eidx[b*2+1] = i1;
        g_ew[b*2]     = w0;  g_ew[b*2+1]   = 1.f - w0;
    }
}

// ---------------- 4) routed expert depthwise 3x3 (4 px / thread) -----------
__global__ void dw_exp_kernel(const float* __restrict__ w,
                              const float* __restrict__ bias) {
    int idx = blockIdx.x * blockDim.x + threadIdx.x;   // over Bn*NK*C*1024
    if (idx >= Bn*NK*C*1024) return;
    int q = idx & 1023;
    int px0 = (q & 15) << 2;
    int py  = q >> 4;
    int rest = idx >> 10;
    int c = rest & 127;
    int k = (rest >> 7) & 1;
    int b = rest >> 8;
    int e = g_eidx[b * NK + k];
    const float* xp = g_xproj + ((((size_t)b * C) + c) << 12);
    const float* wc = w + ((size_t)e * C + c) * 9;
    float bb = bias[e * C + c];
    float acc0 = bb, acc1 = bb, acc2 = bb, acc3 = bb;
    #pragma unroll
    for (int dy = -1; dy <= 1; dy++) {
        int yy = py + dy;
        if ((unsigned)yy >= 64u) continue;
        const float* row = xp + (yy << 6);
        float4 m = *(const float4*)&row[px0];
        float rl = (px0 == 0)  ? 0.f : row[px0 - 1];
        float rr = (px0 == 60) ? 0.f : row[px0 + 4];
        float w0 = wc[(dy+1)*3], w1 = wc[(dy+1)*3+1], w2 = wc[(dy+1)*3+2];
        acc0 += w0*rl  + w1*m.x + w2*m.y;
        acc1 += w0*m.x + w1*m.y + w2*m.z;
        acc2 += w0*m.y + w1*m.z + w2*m.w;
        acc3 += w0*m.z + w1*m.w + w2*rr;
    }
    *(float4*)&g_t2[((size_t)(((b*2 + k) * C) + c) << 12) + (py << 6) + px0] =
        make_float4(acc0, acc1, acc2, acc3);
}

// ---------------- 5) expert pw GEMM x2 (tf32, pipelined) + silu + mix ------
#define WS_E 20     // Wsm stride KC=16: A-frag bank=(20g+t4)%32 conflict-free
__global__ __launch_bounds__(256, 2)
void pw_exp_kernel(const float* __restrict__ Wm, const float* __restrict__ bias,
                   float* __restrict__ out) {
    int b  = blockIdx.y;
    int p0 = blockIdx.x * 64;
    int tx = threadIdx.x;
    int wid = tx >> 5, lane = tx & 31;
    int wm = wid >> 1, wn = wid & 1;
    int g = lane >> 2, t4 = lane & 3;
    int e0 = g_eidx[b*2], e1 = g_eidx[b*2+1];
    float rw0 = g_ew[b*2], rw1 = g_ew[b*2+1];
    __shared__ float Wsm0[128 * WS_E], Wsm1[128 * WS_E];
    __shared__ float Bsm0[16 * BS_S],  Bsm1[16 * BS_S];
    float a0c[2][4][4], a1c[2][4][4];
    #pragma unroll
    for (int i = 0; i < 2; i++)
        #pragma unroll
        for (int j = 0; j < 4; j++)
            #pragma unroll
            for (int l = 0; l < 4; l++) { a0c[i][j][l] = 0.f; a1c[i][j][l] = 0.f; }

    const float* t0 = g_t2 + (((size_t)(b*2 + 0) * C) << 12) + p0;
    const float* t1 = g_t2 + (((size_t)(b*2 + 1) * C) << 12) + p0;
    const float* W0 = Wm + (size_t)e0 * C * C;
    const float* W1 = Wm + (size_t)e1 * C * C;

    int wco[2], wk4[2];
    #pragma unroll
    for (int i = 0; i < 2; i++) { int s = i * 256 + tx; wco[i] = s >> 2; wk4[i] = s & 3; }
    int bk = tx >> 4, bpx = tx & 15;

    float4 wraw0[2], wraw1[2], braw0, braw1;
    #pragma unroll
    for (int i = 0; i < 2; i++) {
        wraw0[i] = *(const float4*)&W0[wco[i] * C + wk4[i] * 4];
        wraw1[i] = *(const float4*)&W1[wco[i] * C + wk4[i] * 4];
    }
    braw0 = *(const float4*)&t0[(size_t)bk * P + bpx * 4];
    braw1 = *(const float4*)&t1[(size_t)bk * P + bpx * 4];

    for (int ci = 0; ci < 8; ci++) {
        #pragma unroll
        for (int i = 0; i < 2; i++) {
            float* d0 = &Wsm0[wco[i] * WS_E + wk4[i] * 4];
            float* d1 = &Wsm1[wco[i] * WS_E + wk4[i] * 4];
            d0[0]=tf32r(wraw0[i].x); d0[1]=tf32r(wraw0[i].y);
            d0[2]=tf32r(wraw0[i].z); d0[3]=tf32r(wraw0[i].w);
            d1[0]=tf32r(wraw1[i].x); d1[1]=tf32r(wraw1[i].y);
            d1[2]=tf32r(wraw1[i].z); d1[3]=tf32r(wraw1[i].w);
        }
        {
            float* d0 = &Bsm0[bk * BS_S + bpx * 4];
            float* d1 = &Bsm1[bk * BS_S + bpx * 4];
            d0[0]=tf32r(braw0.x); d0[1]=tf32r(braw0.y);
            d0[2]=tf32r(braw0.z); d0[3]=tf32r(braw0.w);
            d1[0]=tf32r(braw1.x); d1[1]=tf32r(braw1.y);
            d1[2]=tf32r(braw1.z); d1[3]=tf32r(braw1.w);
        }
        __syncthreads();
        if (ci < 7) {                         // prefetch next chunk
            int c0 = (ci + 1) * 16;
            #pragma unroll
            for (int i = 0; i < 2; i++) {
                wraw0[i] = *(const float4*)&W0[wco[i] * C + c0 + wk4[i] * 4];
                wraw1[i] = *(const float4*)&W1[wco[i] * C + c0 + wk4[i] * 4];
            }
            braw0 = *(const float4*)&t0[(size_t)(c0 + bk) * P + bpx * 4];
            braw1 = *(const float4*)&t1[(size_t)(c0 + bk) * P + bpx * 4];
        }
        #pragma unroll
        for (int kk = 0; kk < 2; kk++) {
            int kb = kk * 8;
            unsigned af0[2][4], af1[2][4];
            #pragma unroll
            for (int mt = 0; mt < 2; mt++) {
                int r0 = wm * 32 + mt * 16 + g;
                af0[mt][0] = __float_as_uint(Wsm0[r0 * WS_E + kb + t4]);
                af0[mt][1] = __float_as_uint(Wsm0[(r0 + 8) * WS_E + kb + t4]);
                af0[mt][2] = __float_as_uint(Wsm0[r0 * WS_E + kb + t4 + 4]);
                af0[mt][3] = __float_as_uint(Wsm0[(r0 + 8) * WS_E + kb + t4 + 4]);
                af1[mt][0] = __float_as_uint(Wsm1[r0 * WS_E + kb + t4]);
                af1[mt][1] = __float_as_uint(Wsm1[(r0 + 8) * WS_E + kb + t4]);
                af1[mt][2] = __float_as_uint(Wsm1[r0 * WS_E + kb + t4 + 4]);
                af1[mt][3] = __float_as_uint(Wsm1[(r0 + 8) * WS_E + kb + t4 + 4]);
            }
            #pragma unroll
            for (int nt = 0; nt < 4; nt++) {
                int col = wn * 32 + nt * 8 + g;
                unsigned b00 = __float_as_uint(Bsm0[(kb + t4) * BS_S + col]);
                unsigned b01 = __float_as_uint(Bsm0[(kb + t4 + 4) * BS_S + col]);
                unsigned b10 = __float_as_uint(Bsm1[(kb + t4) * BS_S + col]);
                unsigned b11 = __float_as_uint(Bsm1[(kb + t4 + 4) * BS_S + col]);
                #pragma unroll
                for (int mt = 0; mt < 2; mt++) {
                    mma_tf32(a0c[mt][nt], af0[mt][0], af0[mt][1], af0[mt][2], af0[mt][3], b00, b01);
                    mma_tf32(a1c[mt][nt], af1[mt][0], af1[mt][1], af1[mt][2], af1[mt][3], b10, b11);
                }
            }
        }
        __syncthreads();
    }
    #pragma unroll
    for (int mt = 0; mt < 2; mt++) {
        int r0 = wm * 32 + mt * 16 + g;
        float b00 = bias[e0 * C + r0], b08 = bias[e0 * C + r0 + 8];
        float b10 = bias[e1 * C + r0], b18 = bias[e1 * C + r0 + 8];
        #pragma unroll
        for (int nt = 0; nt < 4; nt++) {
            int col = p0 + wn * 32 + nt * 8 + 2 * t4;
            float* o0 = out + ((((size_t)b * C) + r0) << 12) + col;
            float* o8 = out + ((((size_t)b * C) + r0 + 8) << 12) + col;
            float v0 = rw0 * silu_f(a0c[mt][nt][0] + b00) + rw1 * silu_f(a1c[mt][nt][0] + b10);
            float v1 = rw0 * silu_f(a0c[mt][nt][1] + b00) + rw1 * silu_f(a1c[mt][nt][1] + b10);
            float v2 = rw0 * silu_f(a0c[mt][nt][2] + b08) + rw1 * silu_f(a1c[mt][nt][2] + b18);
            float v3 = rw0 * silu_f(a0c[mt][nt][3] + b08) + rw1 * silu_f(a1c[mt][nt][3] + b18);
            *(float2*)o0 = make_float2(v0, v1);
            *(float2*)o8 = make_float2(v2, v3);
        }
    }
}

// ---------------- launch ----------------------------------------------------
extern "C" void kernel_launch(void* const* d_in, const int* in_sizes, int n_in,
                              void* d_out, int out_size) {
    const float* x         = (const float*)d_in[0];
    const float* t_emb     = (const float*)d_in[1];
    const float* c_emb     = (const float*)d_in[2];
    const float* proj_dw   = (const float*)d_in[3];
    const float* proj_dw_b = (const float*)d_in[4];
    const float* proj_pw   = (const float*)d_in[5];
    const float* proj_pw_b = (const float*)d_in[6];
    const float* r_w1      = (const float*)d_in[7];
    const float* r_b1      = (const float*)d_in[8];
    const float* r_w2      = (const float*)d_in[9];
    const float* r_b2      = (const float*)d_in[10];
    const float* exp_dw    = (const float*)d_in[11];
    const float* exp_dw_b  = (const float*)d_in[12];
    const float* exp_pw    = (const float*)d_in[13];
    const float* exp_pw_b  = (const float*)d_in[14];

    float* out        = (float*)d_out;
    float* out_logits = out + (size_t)Bn * C * P;

    zero_pooled_kernel<<<(Bn*C + 255) / 256, 256>>>();
    dw_proj_kernel<<<(Bn*C*1024 + 255) / 256, 256>>>(x, proj_dw, proj_dw_b);
    pw_proj_kernel<<<dim3(P / 64, Bn), 256>>>(proj_pw, proj_pw_b);
    router_kernel<<<Bn, 1024>>>(t_emb, c_emb, r_w1, r_b1, r_w2, r_b2, out_logits);
    dw_exp_kernel<<<(Bn*NK*C*1024 + 255) / 256, 256>>>(exp_dw, exp_dw_b);
    pw_exp_kernel<<<dim3(P / 64, Bn), 256>>>(exp_pw, exp_pw_b, out);
}